// round 3
// baseline (speedup 1.0000x reference)
#include <cuda_runtime.h>

#define N_TOK 256
#define D_DIM 128
#define LEAKY_ALPHA 0.2f
#define NEG_INF_V (-9e15f)

#define NWARP 8
#define NCHAIN 2

__global__ void __launch_bounds__(256, 4)
gat_kernel(const float* __restrict__ q, const float* __restrict__ v,
           const int* __restrict__ mask, const float* __restrict__ W,
           const float* __restrict__ bias, float* __restrict__ out)
{
    __shared__ float wm[NWARP];
    __shared__ float ws[NWARP];
    __shared__ float acc_s[NWARP * D_DIM];

    const int row  = blockIdx.x;
    const int tid  = threadIdx.x;
    const int lane = tid & 31;
    const int wid  = tid >> 5;          // 0..7

    const size_t base = (size_t)row * (size_t)(N_TOK * D_DIM);
    const float4* qr = (const float4*)(q + base);
    const float4* vr = (const float4*)(v + base);

    // each lane owns 4 consecutive W entries for the q-part and the v-part
    const float4 Wq = ((const float4*)W)[lane];
    const float4 Wv = ((const float4*)W)[32 + lane];
    const float  bb = __ldg(bias);

    // warp `wid` owns tokens [wid*32, wid*32+32); lane l holds mask of token n0+l
    const int n0   = wid * 32;
    const int mreg = __ldcs(mask + (size_t)row * N_TOK + n0 + lane);

    // NCHAIN independent online-softmax chains per warp (merged exactly later)
    float  m_c[NCHAIN], s_c[NCHAIN];
    float4 a_c[NCHAIN];
    #pragma unroll
    for (int c = 0; c < NCHAIN; ++c) {
        m_c[c] = NEG_INF_V;
        s_c[c] = 0.0f;
        a_c[c] = make_float4(0.f, 0.f, 0.f, 0.f);
    }

    #pragma unroll
    for (int rg = 0; rg < 32 / NCHAIN; ++rg) {
        float4 q4[NCHAIN], v4[NCHAIN];
        #pragma unroll
        for (int c = 0; c < NCHAIN; ++c) {
            const int n = n0 + rg * NCHAIN + c;
            q4[c] = __ldcs(qr + n * 32 + lane);
            v4[c] = __ldcs(vr + n * 32 + lane);
        }
        #pragma unroll
        for (int c = 0; c < NCHAIN; ++c) {
            float p = q4[c].x * Wq.x + q4[c].y * Wq.y
                    + q4[c].z * Wq.z + q4[c].w * Wq.w
                    + v4[c].x * Wv.x + v4[c].y * Wv.y
                    + v4[c].z * Wv.z + v4[c].w * Wv.w;
            #pragma unroll
            for (int off = 16; off; off >>= 1)
                p += __shfl_xor_sync(0xffffffffu, p, off);
            // energy -> leaky relu -> mask (mask via register broadcast)
            float e = p + bb;
            e = (e >= 0.0f) ? e : LEAKY_ALPHA * e;
            const int mk = __shfl_sync(0xffffffffu, mreg, rg * NCHAIN + c);
            const float val = (mk > 0) ? e : NEG_INF_V;
            // 1-exp online softmax update; condition is warp-uniform
            const float d = val - m_c[c];
            if (d <= 0.0f) {
                const float pe = __expf(d);
                s_c[c] += pe;
                a_c[c].x += pe * v4[c].x;  a_c[c].y += pe * v4[c].y;
                a_c[c].z += pe * v4[c].z;  a_c[c].w += pe * v4[c].w;
            } else {
                const float sc = __expf(-d);
                s_c[c] = s_c[c] * sc + 1.0f;
                a_c[c].x = a_c[c].x * sc + v4[c].x;
                a_c[c].y = a_c[c].y * sc + v4[c].y;
                a_c[c].z = a_c[c].z * sc + v4[c].z;
                a_c[c].w = a_c[c].w * sc + v4[c].w;
                m_c[c] = val;
            }
        }
    }

    // ---- merge chains within the warp (m_c/s_c warp-uniform) ----
    float M = m_c[0];
    #pragma unroll
    for (int c = 1; c < NCHAIN; ++c) M = fmaxf(M, m_c[c]);
    float  S = 0.0f;
    float4 A = make_float4(0.f, 0.f, 0.f, 0.f);
    #pragma unroll
    for (int c = 0; c < NCHAIN; ++c) {
        const float f = __expf(m_c[c] - M);
        S   += f * s_c[c];
        A.x += f * a_c[c].x;  A.y += f * a_c[c].y;
        A.z += f * a_c[c].z;  A.w += f * a_c[c].w;
    }

    // ---- merge across warps via smem ----
    if (lane == 0) { wm[wid] = M; ws[wid] = S; }
    ((float4*)(acc_s + wid * D_DIM))[lane] = A;
    __syncthreads();

    if (tid < D_DIM) {
        float gm = wm[0];
        #pragma unroll
        for (int w = 1; w < NWARP; ++w) gm = fmaxf(gm, wm[w]);
        float tot = 0.0f, num = 0.0f;
        #pragma unroll
        for (int w = 0; w < NWARP; ++w) {
            const float f = __expf(wm[w] - gm);
            tot += f * ws[w];
            num += f * acc_s[w * D_DIM + tid];
        }
        out[(size_t)row * D_DIM + tid] = num / tot;
    }
}

extern "C" void kernel_launch(void* const* d_in, const int* in_sizes, int n_in,
                              void* d_out, int out_size)
{
    const float* q    = (const float*)d_in[0];
    const float* v    = (const float*)d_in[1];
    const int*   mask = (const int*)d_in[2];
    const float* W    = (const float*)d_in[3];
    const float* b    = (const float*)d_in[4];
    float* out = (float*)d_out;

    const int rows = in_sizes[0] / (N_TOK * D_DIM);  // B*N = 2048

    gat_kernel<<<rows, 256>>>(q, v, mask, W, b, out);
}

// round 4
// speedup vs baseline: 1.5850x; 1.5850x over previous
#include <cuda_runtime.h>

#define N_TOK 256
#define D_DIM 128
#define LEAKY_ALPHA 0.2f
#define NEG_INF_V (-9e15f)
#define NWARP 8

__global__ void __launch_bounds__(256, 4)
gat_kernel(const float* __restrict__ q, const float* __restrict__ v,
           const int* __restrict__ mask, const float* __restrict__ W,
           const float* __restrict__ bias, float* __restrict__ out)
{
    __shared__ float wm[NWARP];
    __shared__ float ws[NWARP];
    __shared__ float acc_s[NWARP * D_DIM];

    const int row  = blockIdx.x;
    const int tid  = threadIdx.x;
    const int lane = tid & 31;
    const int wid  = tid >> 5;          // 0..7

    const size_t base = (size_t)row * (size_t)(N_TOK * D_DIM);
    const float4* qr = (const float4*)(q + base);
    const float4* vr = (const float4*)(v + base);

    // lane l owns W[l*4..l*4+4) (q part) and W[128+l*4..) (v part)
    const float4 Wq = ((const float4*)W)[lane];
    const float4 Wv = ((const float4*)W)[32 + lane];
    const float  bb = __ldg(bias);

    // warp owns tokens [wid*32, wid*32+32); lane l holds mask bit of token n0+l
    const int n0   = wid * 32;
    const int mreg = __ldcs(mask + (size_t)row * N_TOK + n0 + lane);
    unsigned rem   = __ballot_sync(0xffffffffu, mreg > 0);  // warp-uniform

    // two independent online-softmax chains (merged exactly afterwards)
    float  m0 = NEG_INF_V, s0 = 0.0f;
    float  m1 = NEG_INF_V, s1 = 0.0f;
    float4 a0 = make_float4(0.f, 0.f, 0.f, 0.f);
    float4 a1 = make_float4(0.f, 0.f, 0.f, 0.f);

    // stream ONLY active tokens (masked tokens contribute exactly zero)
    while (rem) {
        const int nA = __ffs(rem) - 1;  rem &= rem - 1;
        int nB = -1;
        if (rem) { nB = __ffs(rem) - 1; rem &= rem - 1; }

        // batch loads ahead of compute
        const float4 qA = __ldcs(qr + (n0 + nA) * 32 + lane);
        const float4 vA = __ldcs(vr + (n0 + nA) * 32 + lane);
        float4 qB, vB;
        if (nB >= 0) {
            qB = __ldcs(qr + (n0 + nB) * 32 + lane);
            vB = __ldcs(vr + (n0 + nB) * 32 + lane);
        }

        // ---- chain 0 : token nA ----
        {
            float p = qA.x * Wq.x + qA.y * Wq.y + qA.z * Wq.z + qA.w * Wq.w
                    + vA.x * Wv.x + vA.y * Wv.y + vA.z * Wv.z + vA.w * Wv.w;
            #pragma unroll
            for (int off = 16; off; off >>= 1)
                p += __shfl_xor_sync(0xffffffffu, p, off);
            float e = p + bb;
            e = (e >= 0.0f) ? e : LEAKY_ALPHA * e;   // token is unmasked
            const float d = e - m0;                   // warp-uniform
            if (d <= 0.0f) {
                const float pe = __expf(d);
                s0 += pe;
                a0.x += pe * vA.x;  a0.y += pe * vA.y;
                a0.z += pe * vA.z;  a0.w += pe * vA.w;
            } else {
                const float sc = __expf(-d);
                s0 = s0 * sc + 1.0f;
                a0.x = a0.x * sc + vA.x;  a0.y = a0.y * sc + vA.y;
                a0.z = a0.z * sc + vA.z;  a0.w = a0.w * sc + vA.w;
                m0 = e;
            }
        }
        // ---- chain 1 : token nB ----
        if (nB >= 0) {
            float p = qB.x * Wq.x + qB.y * Wq.y + qB.z * Wq.z + qB.w * Wq.w
                    + vB.x * Wv.x + vB.y * Wv.y + vB.z * Wv.z + vB.w * Wv.w;
            #pragma unroll
            for (int off = 16; off; off >>= 1)
                p += __shfl_xor_sync(0xffffffffu, p, off);
            float e = p + bb;
            e = (e >= 0.0f) ? e : LEAKY_ALPHA * e;
            const float d = e - m1;
            if (d <= 0.0f) {
                const float pe = __expf(d);
                s1 += pe;
                a1.x += pe * vB.x;  a1.y += pe * vB.y;
                a1.z += pe * vB.z;  a1.w += pe * vB.w;
            } else {
                const float sc = __expf(-d);
                s1 = s1 * sc + 1.0f;
                a1.x = a1.x * sc + vB.x;  a1.y = a1.y * sc + vB.y;
                a1.z = a1.z * sc + vB.z;  a1.w = a1.w * sc + vB.w;
                m1 = e;
            }
        }
    }

    // ---- merge the two chains (m/s warp-uniform) ----
    const float M = fmaxf(m0, m1);
    const float f0 = __expf(m0 - M);     // exp(-inf - -inf) = exp(0) = 1 if both empty
    const float f1 = __expf(m1 - M);
    const float S = f0 * s0 + f1 * s1;
    float4 A;
    A.x = f0 * a0.x + f1 * a1.x;  A.y = f0 * a0.y + f1 * a1.y;
    A.z = f0 * a0.z + f1 * a1.z;  A.w = f0 * a0.w + f1 * a1.w;

    // ---- merge across warps via smem ----
    if (lane == 0) { wm[wid] = M; ws[wid] = S; }
    ((float4*)(acc_s + wid * D_DIM))[lane] = A;
    __syncthreads();

    if (tid < D_DIM) {
        float gm = wm[0];
        #pragma unroll
        for (int w = 1; w < NWARP; ++w) gm = fmaxf(gm, wm[w]);
        float tot = 0.0f, num = 0.0f;
        #pragma unroll
        for (int w = 0; w < NWARP; ++w) {
            const float f = __expf(wm[w] - gm);
            tot += f * ws[w];
            num += f * acc_s[w * D_DIM + tid];
        }
        float r;
        if (tot > 0.0f) {
            r = num / tot;
        } else {
            // all 256 tokens masked: reference softmaxes uniform -> mean(v).
            // Cold path (never taken for this dataset); coalesced across tid.
            float s = 0.0f;
            for (int n = 0; n < N_TOK; ++n)
                s += v[base + (size_t)n * D_DIM + tid];
            r = s * (1.0f / N_TOK);
        }
        out[(size_t)row * D_DIM + tid] = r;
    }
}

extern "C" void kernel_launch(void* const* d_in, const int* in_sizes, int n_in,
                              void* d_out, int out_size)
{
    const float* q    = (const float*)d_in[0];
    const float* v    = (const float*)d_in[1];
    const int*   mask = (const int*)d_in[2];
    const float* W    = (const float*)d_in[3];
    const float* b    = (const float*)d_in[4];
    float* out = (float*)d_out;

    const int rows = in_sizes[0] / (N_TOK * D_DIM);  // B*N = 2048

    gat_kernel<<<rows, 256>>>(q, v, mask, W, b, out);
}

// round 5
// speedup vs baseline: 1.5932x; 1.0052x over previous
#include <cuda_runtime.h>

#define N_TOK 256
#define D_DIM 128
#define LEAKY_ALPHA 0.2f
#define NEG_INF_V (-9e15f)
#define NWARP 8

// online-softmax update of one chain with one unmasked token
__device__ __forceinline__ void chain_update(
    const float4& q4, const float4& v4,
    const float4& Wq, const float4& Wv, float bb,
    float& m, float& s, float4& a)
{
    float p = q4.x * Wq.x + q4.y * Wq.y + q4.z * Wq.z + q4.w * Wq.w
            + v4.x * Wv.x + v4.y * Wv.y + v4.z * Wv.z + v4.w * Wv.w;
    #pragma unroll
    for (int off = 16; off; off >>= 1)
        p += __shfl_xor_sync(0xffffffffu, p, off);
    float e = p + bb;
    e = (e >= 0.0f) ? e : LEAKY_ALPHA * e;
    const float d = e - m;                 // warp-uniform
    if (d <= 0.0f) {
        const float pe = __expf(d);
        s += pe;
        a.x += pe * v4.x;  a.y += pe * v4.y;
        a.z += pe * v4.z;  a.w += pe * v4.w;
    } else {
        const float sc = __expf(-d);
        s = s * sc + 1.0f;
        a.x = a.x * sc + v4.x;  a.y = a.y * sc + v4.y;
        a.z = a.z * sc + v4.z;  a.w = a.w * sc + v4.w;
        m = e;
    }
}

__global__ void __launch_bounds__(256, 3)
gat_kernel(const float* __restrict__ q, const float* __restrict__ v,
           const int* __restrict__ mask, const float* __restrict__ W,
           const float* __restrict__ bias, float* __restrict__ out)
{
    __shared__ float wm[NWARP];
    __shared__ float ws[NWARP];
    __shared__ float acc_s[NWARP * D_DIM];

    const int row  = blockIdx.x;
    const int tid  = threadIdx.x;
    const int lane = tid & 31;
    const int wid  = tid >> 5;          // 0..7

    const size_t base = (size_t)row * (size_t)(N_TOK * D_DIM);
    const float4* qr = (const float4*)(q + base);
    const float4* vr = (const float4*)(v + base);

    const float4 Wq = ((const float4*)W)[lane];
    const float4 Wv = ((const float4*)W)[32 + lane];
    const float  bb = __ldg(bias);

    // warp owns tokens [wid*32, wid*32+32); lane l holds mask bit of n0+l
    const int n0   = wid * 32;
    const int mreg = __ldcs(mask + (size_t)row * N_TOK + n0 + lane);
    unsigned rem   = __ballot_sync(0xffffffffu, mreg > 0);  // warp-uniform

    float  m0 = NEG_INF_V, s0 = 0.0f;
    float  m1 = NEG_INF_V, s1 = 0.0f;
    float4 a0 = make_float4(0.f, 0.f, 0.f, 0.f);
    float4 a1 = make_float4(0.f, 0.f, 0.f, 0.f);

    // ---- software-pipelined stream over ACTIVE tokens only ----
    int nA = -1, nB = -1;
    float4 qA, vA, qB, vB;
    if (rem) {
        nA = __ffs(rem) - 1;  rem &= rem - 1;
        qA = __ldcs(qr + (n0 + nA) * 32 + lane);
        vA = __ldcs(vr + (n0 + nA) * 32 + lane);
    }
    if (rem) {
        nB = __ffs(rem) - 1;  rem &= rem - 1;
        qB = __ldcs(qr + (n0 + nB) * 32 + lane);
        vB = __ldcs(vr + (n0 + nB) * 32 + lane);
    }
    while (rem) {
        // prefetch the next pair BEFORE touching the current pair's data
        const int nC = __ffs(rem) - 1;  rem &= rem - 1;
        const float4 qC = __ldcs(qr + (n0 + nC) * 32 + lane);
        const float4 vC = __ldcs(vr + (n0 + nC) * 32 + lane);
        int nD = -1;
        float4 qD, vD;
        if (rem) {
            nD = __ffs(rem) - 1;  rem &= rem - 1;
            qD = __ldcs(qr + (n0 + nD) * 32 + lane);
            vD = __ldcs(vr + (n0 + nD) * 32 + lane);
        }
        // process current pair while prefetch is in flight
        chain_update(qA, vA, Wq, Wv, bb, m0, s0, a0);
        if (nB >= 0) chain_update(qB, vB, Wq, Wv, bb, m1, s1, a1);
        // rotate
        nA = nC;  qA = qC;  vA = vC;
        nB = nD;
        if (nD >= 0) { qB = qD;  vB = vD; }
    }
    if (nA >= 0) chain_update(qA, vA, Wq, Wv, bb, m0, s0, a0);
    if (nB >= 0) chain_update(qB, vB, Wq, Wv, bb, m1, s1, a1);

    // ---- merge the two chains (warp-uniform) ----
    const float M  = fmaxf(m0, m1);
    const float f0 = __expf(m0 - M);
    const float f1 = __expf(m1 - M);
    const float S  = f0 * s0 + f1 * s1;
    float4 A;
    A.x = f0 * a0.x + f1 * a1.x;  A.y = f0 * a0.y + f1 * a1.y;
    A.z = f0 * a0.z + f1 * a1.z;  A.w = f0 * a0.w + f1 * a1.w;

    // ---- merge across warps via smem ----
    if (lane == 0) { wm[wid] = M; ws[wid] = S; }
    ((float4*)(acc_s + wid * D_DIM))[lane] = A;
    __syncthreads();

    if (tid < D_DIM) {
        float gm = wm[0];
        #pragma unroll
        for (int w = 1; w < NWARP; ++w) gm = fmaxf(gm, wm[w]);
        float tot = 0.0f, num = 0.0f;
        #pragma unroll
        for (int w = 0; w < NWARP; ++w) {
            const float f = __expf(wm[w] - gm);
            tot += f * ws[w];
            num += f * acc_s[w * D_DIM + tid];
        }
        float r;
        if (tot > 0.0f) {
            r = num / tot;
        } else {
            // all tokens masked: reference -> uniform softmax -> mean(v).
            // Cold path; coalesced across tid.
            float s = 0.0f;
            for (int n = 0; n < N_TOK; ++n)
                s += v[base + (size_t)n * D_DIM + tid];
            r = s * (1.0f / N_TOK);
        }
        out[(size_t)row * D_DIM + tid] = r;
    }
}

extern "C" void kernel_launch(void* const* d_in, const int* in_sizes, int n_in,
                              void* d_out, int out_size)
{
    const float* q    = (const float*)d_in[0];
    const float* v    = (const float*)d_in[1];
    const int*   mask = (const int*)d_in[2];
    const float* W    = (const float*)d_in[3];
    const float* b    = (const float*)d_in[4];
    float* out = (float*)d_out;

    const int rows = in_sizes[0] / (N_TOK * D_DIM);  // B*N = 2048

    gat_kernel<<<rows, 256>>>(q, v, mask, W, b, out);
}